// round 3
// baseline (speedup 1.0000x reference)
#include <cuda_runtime.h>
#include <math.h>

// Problem constants
#define M_TOK   32768            // 8*4096 input vectors
#define KVOC    8192             // vocab
#define CD      512              // dim
#define MOMENTUM 0.995f

// Output layout (concatenated tuple, float32):
// x_q [M_TOK*CD], loss [1], perplexity [1], new_dict [KVOC*CD], new_counts [KVOC]
#define OQ 0
#define OL 16777216
#define OP 16777217
#define OD 16777218
#define OC 20971522
// NOTE: OD and OC are ≡ 2 (mod 4) elements → those regions are only 8-byte
// aligned relative to a 16B-aligned base. float2/scalars only there.

// ---------------- scratch (no allocations allowed) ----------------
__device__ float               g_e[KVOC * CD];      // codewords dict/counts (16 MB)
__device__ float               g_nsq[KVOC];         // ||e_k||^2
__device__ float               g_s1[M_TOK];         // ||x_m||^2
__device__ unsigned long long  g_best[M_TOK];       // packed (f32bits(d)<<32)|k
__device__ int                 g_cnt[KVOC];         // histogram
__device__ double              g_loss;              // sum of (x_q - x)^2
__device__ double              g_csum;              // sum of new_counts

// ---------------- reductions ----------------
__device__ __forceinline__ float blkSum128(float v) {
    __shared__ float sh[4];
    #pragma unroll
    for (int o = 16; o; o >>= 1) v += __shfl_down_sync(0xffffffffu, v, o);
    if ((threadIdx.x & 31) == 0) sh[threadIdx.x >> 5] = v;
    __syncthreads();
    if (threadIdx.x == 0) v = sh[0] + sh[1] + sh[2] + sh[3];
    return v;  // valid on thread 0 only
}

__device__ __forceinline__ double blkSum1024d(double v) {
    __shared__ double sh[32];
    #pragma unroll
    for (int o = 16; o; o >>= 1) v += __shfl_down_sync(0xffffffffu, v, o);
    if ((threadIdx.x & 31) == 0) sh[threadIdx.x >> 5] = v;
    __syncthreads();
    if (threadIdx.x < 32) {
        v = sh[threadIdx.x];
        #pragma unroll
        for (int o = 16; o; o >>= 1) v += __shfl_down_sync(0xffffffffu, v, o);
    }
    return v;  // valid on thread 0 only
}

// ---------------- K1: codewords, norms, new_dict init, zero accumulators ----
// grid = KVOC blocks, 128 threads (one float4 of the row per thread)
__global__ void k_prep_codes(const float* __restrict__ dict,
                             const float* __restrict__ counts,
                             float* __restrict__ out) {
    int k = blockIdx.x;
    int t = threadIdx.x;
    float cn = counts[k];
    float4 d4 = ((const float4*)&dict[(size_t)k * CD])[t];
    float4 e4;
    // mimic reference element-wise division
    e4.x = __fdiv_rn(d4.x, cn);
    e4.y = __fdiv_rn(d4.y, cn);
    e4.z = __fdiv_rn(d4.z, cn);
    e4.w = __fdiv_rn(d4.w, cn);
    ((float4*)&g_e[(size_t)k * CD])[t] = e4;

    // new_dict initialized to dictionary*MOMENTUM (x_sum scattered later).
    // OD region is only 8B-aligned -> float2 stores.
    float* ndrow = &out[OD + (size_t)k * CD + t * 4];
    float2 nd0, nd1;
    nd0.x = __fmul_rn(d4.x, MOMENTUM);
    nd0.y = __fmul_rn(d4.y, MOMENTUM);
    nd1.x = __fmul_rn(d4.z, MOMENTUM);
    nd1.y = __fmul_rn(d4.w, MOMENTUM);
    ((float2*)ndrow)[0] = nd0;
    ((float2*)ndrow)[1] = nd1;

    float p = e4.x * e4.x + e4.y * e4.y + e4.z * e4.z + e4.w * e4.w;
    float tot = blkSum128(p);
    if (t == 0) {
        g_nsq[k] = tot;
        g_cnt[k] = 0;
        if (k == 0) { g_loss = 0.0; g_csum = 0.0; }
    }
}

// ---------------- K2: row norms ||x||^2 + init best ----------------
// grid = M_TOK blocks, 128 threads
__global__ void k_prep_rows(const float* __restrict__ X) {
    int m = blockIdx.x;
    int t = threadIdx.x;
    float4 v = ((const float4*)&X[(size_t)m * CD])[t];
    float p = v.x * v.x + v.y * v.y + v.z * v.z + v.w * v.w;
    float tot = blkSum128(p);
    if (t == 0) {
        g_s1[m] = tot;
        g_best[m] = 0xFFFFFFFFFFFFFFFFULL;
    }
}

// ---------------- K3: distance GEMM + argmin epilogue ----------------
// BM=128 rows x BN=128 codes per block, 256 threads, 8x8 per thread, BK=16
#define BM 128
#define BN 128
#define BKC 16

__global__ void __launch_bounds__(256)
k_argmin(const float* __restrict__ X) {
    __shared__ float As[BKC][BM + 4];
    __shared__ float Bs[BKC][BN + 4];
    __shared__ unsigned long long sb[BM];

    const int t  = threadIdx.x;
    const int tx = t & 15;       // code-tile lane
    const int ty = t >> 4;       // row-tile lane
    const int nBase = blockIdx.x * BN;
    const int mBase = blockIdx.y * BM;

    if (t < BM) sb[t] = 0xFFFFFFFFFFFFFFFFULL;

    float acc[8][8];
    #pragma unroll
    for (int i = 0; i < 8; i++)
        #pragma unroll
        for (int j = 0; j < 8; j++) acc[i][j] = 0.0f;

    for (int c0 = 0; c0 < CD; c0 += BKC) {
        // stage X tile (transposed) : 512 float4 loads by 256 threads
        #pragma unroll
        for (int s = 0; s < 2; s++) {
            int f   = t + s * 256;
            int row = f >> 2;
            int c4  = (f & 3) * 4;
            float4 v = *(const float4*)&X[(size_t)(mBase + row) * CD + c0 + c4];
            As[c4 + 0][row] = v.x; As[c4 + 1][row] = v.y;
            As[c4 + 2][row] = v.z; As[c4 + 3][row] = v.w;
        }
        // stage E tile (transposed)
        #pragma unroll
        for (int s = 0; s < 2; s++) {
            int f   = t + s * 256;
            int row = f >> 2;
            int c4  = (f & 3) * 4;
            float4 v = *(const float4*)&g_e[(size_t)(nBase + row) * CD + c0 + c4];
            Bs[c4 + 0][row] = v.x; Bs[c4 + 1][row] = v.y;
            Bs[c4 + 2][row] = v.z; Bs[c4 + 3][row] = v.w;
        }
        __syncthreads();

        #pragma unroll
        for (int kk = 0; kk < BKC; kk++) {
            float a[8], b[8];
            *(float4*)&a[0] = *(const float4*)&As[kk][ty * 8];
            *(float4*)&a[4] = *(const float4*)&As[kk][ty * 8 + 4];
            *(float4*)&b[0] = *(const float4*)&Bs[kk][tx * 8];
            *(float4*)&b[4] = *(const float4*)&Bs[kk][tx * 8 + 4];
            #pragma unroll
            for (int i = 0; i < 8; i++)
                #pragma unroll
                for (int j = 0; j < 8; j++)
                    acc[i][j] = fmaf(a[i], b[j], acc[i][j]);
        }
        __syncthreads();
    }

    // epilogue: d = (S1 - 2*dot) + nsq, first-index argmin via packed key
    float nsq[8];
    #pragma unroll
    for (int j = 0; j < 8; j++) nsq[j] = g_nsq[nBase + tx * 8 + j];

    #pragma unroll
    for (int i = 0; i < 8; i++) {
        int mloc = ty * 8 + i;
        float s1 = g_s1[mBase + mloc];
        unsigned long long lb = 0xFFFFFFFFFFFFFFFFULL;
        #pragma unroll
        for (int j = 0; j < 8; j++) {
            unsigned n = (unsigned)(nBase + tx * 8 + j);
            // mimic reference rounding structure: (S1 - 2*dot) + nsq
            float td = __fmul_rn(2.0f, acc[i][j]);
            float d  = __fadd_rn(__fsub_rn(s1, td), nsq[j]);
            unsigned long long key =
                ((unsigned long long)__float_as_uint(d) << 32) | n;
            lb = lb < key ? lb : key;
        }
        atomicMin(&sb[mloc], lb);
    }
    __syncthreads();
    if (t < BM) atomicMin(&g_best[mBase + t], sb[t]);
}

// ---------------- K4: gather x_q, scatter x_sum, histogram, loss ----------
// grid = M_TOK blocks, 128 threads
__global__ void k_assign(const float* __restrict__ X, float* __restrict__ out) {
    int m = blockIdx.x;
    int t = threadIdx.x;
    int id = (int)(g_best[m] & 0x1FFFULL);  // k < 8192 always

    float4 x4 = ((const float4*)&X[(size_t)m * CD])[t];
    float4 e4 = ((const float4*)&g_e[(size_t)id * CD])[t];

    // straight-through value: x + (e - x), mimic fp32 ops
    float4 q;
    q.x = __fadd_rn(x4.x, __fsub_rn(e4.x, x4.x));
    q.y = __fadd_rn(x4.y, __fsub_rn(e4.y, x4.y));
    q.z = __fadd_rn(x4.z, __fsub_rn(e4.z, x4.z));
    q.w = __fadd_rn(x4.w, __fsub_rn(e4.w, x4.w));
    ((float4*)&out[OQ + (size_t)m * CD])[t] = q;

    float dx = __fsub_rn(q.x, x4.x);
    float dy = __fsub_rn(q.y, x4.y);
    float dz = __fsub_rn(q.z, x4.z);
    float dw = __fsub_rn(q.w, x4.w);
    float ls = dx * dx + dy * dy + dz * dz + dw * dw;

    // scatter x into new_dict (OD region: scalar atomics, 4B aligned always)
    float* nd = &out[OD + (size_t)id * CD + t * 4];
    atomicAdd(&nd[0], x4.x);
    atomicAdd(&nd[1], x4.y);
    atomicAdd(&nd[2], x4.z);
    atomicAdd(&nd[3], x4.w);

    float tot = blkSum128(ls);
    if (t == 0) {
        atomicAdd(&g_loss, (double)tot);
        atomicAdd(&g_cnt[id], 1);
    }
}

// ---------------- K5a: new_counts + total ----------------
__global__ void k_counts(const float* __restrict__ counts, float* __restrict__ out) {
    int t = threadIdx.x;
    double s = 0.0;
    for (int k = t; k < KVOC; k += 1024) {
        float nc = __fadd_rn(__fmul_rn(counts[k], MOMENTUM), (float)g_cnt[k]);
        out[OC + k] = nc;
        s += (double)nc;
    }
    double tot = blkSum1024d(s);
    if (t == 0) g_csum = tot;
}

// ---------------- K5b: perplexity + loss finalize ----------------
__global__ void k_final(float* __restrict__ out) {
    int t = threadIdx.x;
    double tot = g_csum;
    double ent = 0.0;
    for (int k = t; k < KVOC; k += 1024) {
        double p = (double)out[OC + k] / tot;
        ent += p * log(p + 1e-10);
    }
    double e = blkSum1024d(ent);
    if (t == 0) {
        out[OP] = (float)exp(-e);
        out[OL] = (float)(0.25 * g_loss / 16777216.0);
    }
}

// ---------------- launch ----------------
extern "C" void kernel_launch(void* const* d_in, const int* in_sizes, int n_in,
                              void* d_out, int out_size) {
    const float* x      = (const float*)d_in[0];
    const float* dict   = (const float*)d_in[1];
    const float* counts = (const float*)d_in[2];
    float* out = (float*)d_out;

    k_prep_codes<<<KVOC, 128>>>(dict, counts, out);
    k_prep_rows<<<M_TOK, 128>>>(x);
    dim3 g3(KVOC / BN, M_TOK / BM);
    k_argmin<<<g3, 256>>>(x);
    k_assign<<<M_TOK, 128>>>(x, out);
    k_counts<<<1, 1024>>>(counts, out);
    k_final<<<1, 1024>>>(out);
}

// round 7
// speedup vs baseline: 1.3132x; 1.3132x over previous
#include <cuda_runtime.h>
#include <math.h>
#include <stdint.h>

// Problem constants
#define M_TOK   32768
#define KVOC    8192
#define CD      512
#define MOMENTUM 0.995f

// Output layout (concatenated tuple, float32)
#define OQ 0
#define OL 16777216
#define OP 16777217
#define OD 16777218
#define OC 20971522
// OD/OC are == 2 (mod 4) elements -> 8B-aligned only. float2/scalars there.

// ---------------- scratch ----------------
__device__ __align__(128) float g_e[KVOC * CD];
__device__ float               g_nsq[KVOC];
__device__ float               g_s1[M_TOK];
__device__ unsigned long long  g_best[M_TOK];
__device__ int                 g_cnt[KVOC];
__device__ double              g_loss;
__device__ double              g_csum;

// ---------------- helpers ----------------
__device__ __forceinline__ float blkSum128(float v) {
    __shared__ float sh[4];
    #pragma unroll
    for (int o = 16; o; o >>= 1) v += __shfl_down_sync(0xffffffffu, v, o);
    if ((threadIdx.x & 31) == 0) sh[threadIdx.x >> 5] = v;
    __syncthreads();
    if (threadIdx.x == 0) v = sh[0] + sh[1] + sh[2] + sh[3];
    return v;
}
__device__ __forceinline__ double blkSum1024d(double v) {
    __shared__ double sh[32];
    #pragma unroll
    for (int o = 16; o; o >>= 1) v += __shfl_down_sync(0xffffffffu, v, o);
    if ((threadIdx.x & 31) == 0) sh[threadIdx.x >> 5] = v;
    __syncthreads();
    if (threadIdx.x < 32) {
        v = sh[threadIdx.x];
        #pragma unroll
        for (int o = 16; o; o >>= 1) v += __shfl_down_sync(0xffffffffu, v, o);
    }
    return v;
}
__device__ __forceinline__ uint32_t smem_u32(const void* p) {
    uint32_t a;
    asm("{ .reg .u64 t; cvta.to.shared.u64 t, %1; cvt.u32.u64 %0, t; }" : "=r"(a) : "l"(p));
    return a;
}
__device__ __forceinline__ void cp16(uint32_t sdst, const void* gsrc) {
    asm volatile("cp.async.cg.shared.global [%0], [%1], 16;" :: "r"(sdst), "l"(gsrc));
}
// split fp32 x into tf32-exact hi and tf32-rounded residual lo
__device__ __forceinline__ void splitf(float x, uint32_t& h, uint32_t& l) {
    uint32_t xb = __float_as_uint(x);
    h = xb & 0xFFFFE000u;
    float lof = __fsub_rn(x, __uint_as_float(h));
    asm("cvt.rna.tf32.f32 %0, %1;" : "=r"(l) : "f"(lof));
}
__device__ __forceinline__ void mma8(float* c, const uint32_t* a, const uint32_t* b) {
    asm volatile(
        "mma.sync.aligned.m16n8k8.row.col.f32.tf32.tf32.f32 "
        "{%0,%1,%2,%3}, {%4,%5,%6,%7}, {%8,%9}, {%0,%1,%2,%3};"
        : "+f"(c[0]), "+f"(c[1]), "+f"(c[2]), "+f"(c[3])
        : "r"(a[0]), "r"(a[1]), "r"(a[2]), "r"(a[3]), "r"(b[0]), "r"(b[1]));
}

// ---------------- K1: codewords, norms, new_dict init ----------------
__global__ void k_prep_codes(const float* __restrict__ dict,
                             const float* __restrict__ counts,
                             float* __restrict__ out) {
    int k = blockIdx.x;
    int t = threadIdx.x;
    float cn = counts[k];
    float4 d4 = ((const float4*)&dict[(size_t)k * CD])[t];
    float4 e4;
    e4.x = __fdiv_rn(d4.x, cn); e4.y = __fdiv_rn(d4.y, cn);
    e4.z = __fdiv_rn(d4.z, cn); e4.w = __fdiv_rn(d4.w, cn);
    ((float4*)&g_e[(size_t)k * CD])[t] = e4;

    float* ndrow = &out[OD + (size_t)k * CD + t * 4];
    float2 nd0, nd1;
    nd0.x = __fmul_rn(d4.x, MOMENTUM); nd0.y = __fmul_rn(d4.y, MOMENTUM);
    nd1.x = __fmul_rn(d4.z, MOMENTUM); nd1.y = __fmul_rn(d4.w, MOMENTUM);
    ((float2*)ndrow)[0] = nd0;
    ((float2*)ndrow)[1] = nd1;

    float p = e4.x * e4.x + e4.y * e4.y + e4.z * e4.z + e4.w * e4.w;
    float tot = blkSum128(p);
    if (t == 0) {
        g_nsq[k] = tot;
        g_cnt[k] = 0;
        if (k == 0) { g_loss = 0.0; g_csum = 0.0; }
    }
}

// ---------------- K2: row norms + init best ----------------
__global__ void k_prep_rows(const float* __restrict__ X) {
    int m = blockIdx.x;
    int t = threadIdx.x;
    float4 v = ((const float4*)&X[(size_t)m * CD])[t];
    float p = v.x * v.x + v.y * v.y + v.z * v.z + v.w * v.w;
    float tot = blkSum128(p);
    if (t == 0) {
        g_s1[m] = tot;
        g_best[m] = 0xFFFFFFFFFFFFFFFFULL;
    }
}

// ---------------- K3: 3xTF32 mma.sync distance GEMM + argmin ----------------
// CTA tile 128(M)x128(N), BK=32, 256 thr = 8 warps (2x4), warp tile 64x32.
#define TBM 128
#define TBN 128
#define BKC 32
#define NCHUNK (CD / BKC)          // 16
#define ROWF 36                    // floats per smem row (32 + 4 pad)
#define ROWB (ROWF * 4)            // 144 bytes
#define A_BYTES (TBM * ROWB)       // 18432
#define STAGE_BYTES (2 * A_BYTES)  // A + B = 36864
#define SMEM_TOTAL (2 * STAGE_BYTES)

__global__ void __launch_bounds__(256)
k_mma_argmin(const float* __restrict__ X) {
    extern __shared__ char smem[];
    const uint32_t sbase = smem_u32(smem);
    const int t    = threadIdx.x;
    const int lane = t & 31;
    const int wid  = t >> 5;
    const int wm   = wid & 1;      // 2 warp rows (M)
    const int wn   = wid >> 1;     // 4 warp cols (N)
    const int mB   = blockIdx.y * TBM;
    const int nB   = blockIdx.x * TBN;

    const int grp = lane >> 2;     // 0..7
    const int qid = lane & 3;      // 0..3

    float acc[4][4][4];
    #pragma unroll
    for (int i = 0; i < 4; i++)
        #pragma unroll
        for (int j = 0; j < 4; j++)
            #pragma unroll
            for (int r = 0; r < 4; r++) acc[i][j][r] = 0.0f;

    const float* Eg = g_e;
    #define STAGE_CHUNK(CHUNK, BUF)                                               \
        {                                                                         \
            int c0 = (CHUNK) * BKC;                                               \
            uint32_t sa = sbase + (BUF) * STAGE_BYTES;                            \
            uint32_t sbb = sa + A_BYTES;                                          \
            _Pragma("unroll")                                                     \
            for (int q = 0; q < 4; q++) {                                         \
                int id  = t + q * 256;                                            \
                int row = id >> 3;                                                \
                int c4  = (id & 7) * 4;                                           \
                cp16(sa + row * ROWB + c4 * 4,                                    \
                     X + (size_t)(mB + row) * CD + c0 + c4);                      \
                cp16(sbb + row * ROWB + c4 * 4,                                   \
                     Eg + (size_t)(nB + row) * CD + c0 + c4);                     \
            }                                                                     \
            asm volatile("cp.async.commit_group;");                               \
        }

    STAGE_CHUNK(0, 0);

    for (int ch = 0; ch < NCHUNK; ch++) {
        int buf = ch & 1;
        if (ch + 1 < NCHUNK) {
            STAGE_CHUNK(ch + 1, (ch + 1) & 1);
            asm volatile("cp.async.wait_group 1;");
        } else {
            asm volatile("cp.async.wait_group 0;");
        }
        __syncthreads();

        const float* As = (const float*)(smem + buf * STAGE_BYTES);
        const float* Bs = (const float*)(smem + buf * STAGE_BYTES + A_BYTES);

        #pragma unroll
        for (int ks = 0; ks < 4; ks++) {
            const int kk = ks * 8 + qid;
            uint32_t Ah[4][4], Al[4][4], Bh[4][2], Bl[4][2];
            #pragma unroll
            for (int i = 0; i < 4; i++) {
                int r = wm * 64 + i * 16 + grp;
                splitf(As[r * ROWF + kk],           Ah[i][0], Al[i][0]);
                splitf(As[(r + 8) * ROWF + kk],     Ah[i][1], Al[i][1]);
                splitf(As[r * ROWF + kk + 4],       Ah[i][2], Al[i][2]);
                splitf(As[(r + 8) * ROWF + kk + 4], Ah[i][3], Al[i][3]);
            }
            #pragma unroll
            for (int j = 0; j < 4; j++) {
                int r = wn * 32 + j * 8 + grp;
                splitf(Bs[r * ROWF + kk],     Bh[j][0], Bl[j][0]);
                splitf(Bs[r * ROWF + kk + 4], Bh[j][1], Bl[j][1]);
            }
            // fused issue: each acc[i][j] receives hh, hl, lh (in that order)
            #pragma unroll
            for (int i = 0; i < 4; i++)
                #pragma unroll
                for (int j = 0; j < 4; j++) {
                    mma8(acc[i][j], Ah[i], Bh[j]);
                    mma8(acc[i][j], Ah[i], Bl[j]);
                    mma8(acc[i][j], Al[i], Bh[j]);
                }
        }
        __syncthreads();
    }

    // epilogue: d = (s1 - 2*dot) + nsq (exact R3 op order), packed-key argmin
    #pragma unroll
    for (int i = 0; i < 4; i++) {
        int r0 = mB + wm * 64 + i * 16 + grp;
        int r1 = r0 + 8;
        float s10 = g_s1[r0];
        float s11 = g_s1[r1];
        unsigned long long k0 = 0xFFFFFFFFFFFFFFFFULL;
        unsigned long long k1 = 0xFFFFFFFFFFFFFFFFULL;
        #pragma unroll
        for (int j = 0; j < 4; j++) {
            int n0 = nB + wn * 32 + j * 8 + 2 * qid;
            float q0 = g_nsq[n0];
            float q1 = g_nsq[n0 + 1];
            float d00 = __fadd_rn(__fsub_rn(s10, __fmul_rn(2.0f, acc[i][j][0])), q0);
            float d01 = __fadd_rn(__fsub_rn(s10, __fmul_rn(2.0f, acc[i][j][1])), q1);
            float d10 = __fadd_rn(__fsub_rn(s11, __fmul_rn(2.0f, acc[i][j][2])), q0);
            float d11 = __fadd_rn(__fsub_rn(s11, __fmul_rn(2.0f, acc[i][j][3])), q1);
            unsigned long long c;
            c = ((unsigned long long)__float_as_uint(d00) << 32) | (unsigned)n0;
            k0 = k0 < c ? k0 : c;
            c = ((unsigned long long)__float_as_uint(d01) << 32) | (unsigned)(n0 + 1);
            k0 = k0 < c ? k0 : c;
            c = ((unsigned long long)__float_as_uint(d10) << 32) | (unsigned)n0;
            k1 = k1 < c ? k1 : c;
            c = ((unsigned long long)__float_as_uint(d11) << 32) | (unsigned)(n0 + 1);
            k1 = k1 < c ? k1 : c;
        }
        // quad reduction (lanes 4q..4q+3 share rows r0,r1)
        #pragma unroll
        for (int o = 1; o <= 2; o <<= 1) {
            unsigned long long s0 = __shfl_xor_sync(0xffffffffu, k0, o);
            unsigned long long s1v = __shfl_xor_sync(0xffffffffu, k1, o);
            k0 = k0 < s0 ? k0 : s0;
            k1 = k1 < s1v ? k1 : s1v;
        }
        if (qid == 0) {
            atomicMin(&g_best[r0], k0);
            atomicMin(&g_best[r1], k1);
        }
    }
}

// ---------------- K4: gather x_q, scatter x_sum, histogram, loss ----------
__global__ void k_assign(const float* __restrict__ X, float* __restrict__ out) {
    int m = blockIdx.x;
    int t = threadIdx.x;
    int id = (int)(g_best[m] & 0x1FFFULL);

    float4 x4 = ((const float4*)&X[(size_t)m * CD])[t];
    float4 e4 = ((const float4*)&g_e[(size_t)id * CD])[t];

    float4 q;
    q.x = __fadd_rn(x4.x, __fsub_rn(e4.x, x4.x));
    q.y = __fadd_rn(x4.y, __fsub_rn(e4.y, x4.y));
    q.z = __fadd_rn(x4.z, __fsub_rn(e4.z, x4.z));
    q.w = __fadd_rn(x4.w, __fsub_rn(e4.w, x4.w));
    ((float4*)&out[OQ + (size_t)m * CD])[t] = q;

    float dx = __fsub_rn(q.x, x4.x), dy = __fsub_rn(q.y, x4.y);
    float dz = __fsub_rn(q.z, x4.z), dw = __fsub_rn(q.w, x4.w);
    float ls = dx * dx + dy * dy + dz * dz + dw * dw;

    float* nd = &out[OD + (size_t)id * CD + t * 4];
    atomicAdd(&nd[0], x4.x);
    atomicAdd(&nd[1], x4.y);
    atomicAdd(&nd[2], x4.z);
    atomicAdd(&nd[3], x4.w);

    float tot = blkSum128(ls);
    if (t == 0) {
        atomicAdd(&g_loss, (double)tot);
        atomicAdd(&g_cnt[id], 1);
    }
}

// ---------------- K5a/K5b: counts, perplexity, loss ----------------
__global__ void k_counts(const float* __restrict__ counts, float* __restrict__ out) {
    int t = threadIdx.x;
    double s = 0.0;
    for (int k = t; k < KVOC; k += 1024) {
        float nc = __fadd_rn(__fmul_rn(counts[k], MOMENTUM), (float)g_cnt[k]);
        out[OC + k] = nc;
        s += (double)nc;
    }
    double tot = blkSum1024d(s);
    if (t == 0) g_csum = tot;
}
__global__ void k_final(float* __restrict__ out) {
    int t = threadIdx.x;
    double tot = g_csum;
    double ent = 0.0;
    for (int k = t; k < KVOC; k += 1024) {
        double p = (double)out[OC + k] / tot;
        ent += p * log(p + 1e-10);
    }
    double e = blkSum1024d(ent);
    if (t == 0) {
        out[OP] = (float)exp(-e);
        out[OL] = (float)(0.25 * g_loss / 16777216.0);
    }
}

// ---------------- launch ----------------
extern "C" void kernel_launch(void* const* d_in, const int* in_sizes, int n_in,
                              void* d_out, int out_size) {
    const float* x      = (const float*)d_in[0];
    const float* dict   = (const float*)d_in[1];
    const float* counts = (const float*)d_in[2];
    float* out = (float*)d_out;

    // Idempotent, host-side, capture-safe; called every time (no static guards).
    cudaFuncSetAttribute(k_mma_argmin, cudaFuncAttributeMaxDynamicSharedMemorySize,
                         SMEM_TOTAL);

    k_prep_codes<<<KVOC, 128>>>(dict, counts, out);
    k_prep_rows<<<M_TOK, 128>>>(x);
    dim3 gm(KVOC / TBN, M_TOK / TBM);
    k_mma_argmin<<<gm, 256, SMEM_TOTAL>>>(x);
    k_assign<<<M_TOK, 128>>>(x, out);
    k_counts<<<1, 1024>>>(counts, out);
    k_final<<<1, 1024>>>(out);
}

// round 8
// speedup vs baseline: 2.3654x; 1.8013x over previous
#include <cuda_runtime.h>
#include <cuda_bf16.h>
#include <math.h>
#include <stdint.h>

// Problem constants
#define M_TOK   32768
#define KVOC    8192
#define CD      512
#define MOMENTUM 0.995f

// Output layout (concatenated tuple, float32)
#define OQ 0
#define OL 16777216
#define OP 16777217
#define OD 16777218
#define OC 20971522
// OD/OC are == 2 (mod 4) elements -> 8B-aligned only. float2/scalars there.

// ---------------- scratch ----------------
__device__ __align__(128) float g_e[KVOC * CD];
__device__ __align__(128) __nv_bfloat162 g_xh[M_TOK * CD / 2];
__device__ __align__(128) __nv_bfloat162 g_xl[M_TOK * CD / 2];
__device__ __align__(128) __nv_bfloat162 g_eh[KVOC * CD / 2];
__device__ __align__(128) __nv_bfloat162 g_el[KVOC * CD / 2];
__device__ float               g_nsq[KVOC];
__device__ float               g_s1[M_TOK];
__device__ unsigned long long  g_best[M_TOK];
__device__ int                 g_cnt[KVOC];
__device__ double              g_loss;
__device__ double              g_csum;

// ---------------- helpers ----------------
__device__ __forceinline__ float blkSum128(float v) {
    __shared__ float sh[4];
    #pragma unroll
    for (int o = 16; o; o >>= 1) v += __shfl_down_sync(0xffffffffu, v, o);
    if ((threadIdx.x & 31) == 0) sh[threadIdx.x >> 5] = v;
    __syncthreads();
    if (threadIdx.x == 0) v = sh[0] + sh[1] + sh[2] + sh[3];
    return v;
}
__device__ __forceinline__ double blkSum1024d(double v) {
    __shared__ double sh[32];
    #pragma unroll
    for (int o = 16; o; o >>= 1) v += __shfl_down_sync(0xffffffffu, v, o);
    if ((threadIdx.x & 31) == 0) sh[threadIdx.x >> 5] = v;
    __syncthreads();
    if (threadIdx.x < 32) {
        v = sh[threadIdx.x];
        #pragma unroll
        for (int o = 16; o; o >>= 1) v += __shfl_down_sync(0xffffffffu, v, o);
    }
    return v;
}
__device__ __forceinline__ uint32_t smem_u32(const void* p) {
    uint32_t a;
    asm("{ .reg .u64 t; cvta.to.shared.u64 t, %1; cvt.u32.u64 %0, t; }" : "=r"(a) : "l"(p));
    return a;
}
__device__ __forceinline__ void cp16(uint32_t sdst, const void* gsrc) {
    asm volatile("cp.async.cg.shared.global [%0], [%1], 16;" :: "r"(sdst), "l"(gsrc));
}
// bf16 split of a float2: h = bf16 pair, l = bf16(residual) pair (lo half = first elem)
__device__ __forceinline__ void split2(float x0, float x1, __nv_bfloat162& h, __nv_bfloat162& l) {
    h = __floats2bfloat162_rn(x0, x1);
    float2 hb = __bfloat1622float2(h);
    l = __floats2bfloat162_rn(__fsub_rn(x0, hb.x), __fsub_rn(x1, hb.y));
}
__device__ __forceinline__ void mma16(float* c, const uint32_t* a, const uint32_t* b) {
    asm volatile(
        "mma.sync.aligned.m16n8k16.row.col.f32.bf16.bf16.f32 "
        "{%0,%1,%2,%3}, {%4,%5,%6,%7}, {%8,%9}, {%0,%1,%2,%3};"
        : "+f"(c[0]), "+f"(c[1]), "+f"(c[2]), "+f"(c[3])
        : "r"(a[0]), "r"(a[1]), "r"(a[2]), "r"(a[3]), "r"(b[0]), "r"(b[1]));
}

// ---------------- K0: split X into bf16 hi/lo pairs ----------------
__global__ void k_split_x(const float* __restrict__ X) {
    size_t i = (size_t)blockIdx.x * 256 + threadIdx.x;   // float4 index
    float4 v = ((const float4*)X)[i];
    __nv_bfloat162 h0, l0, h1, l1;
    split2(v.x, v.y, h0, l0);
    split2(v.z, v.w, h1, l1);
    g_xh[i * 2] = h0; g_xh[i * 2 + 1] = h1;
    g_xl[i * 2] = l0; g_xl[i * 2 + 1] = l1;
}

// ---------------- K1: codewords, norms, bf16 splits, new_dict init --------
__global__ void k_prep_codes(const float* __restrict__ dict,
                             const float* __restrict__ counts,
                             float* __restrict__ out) {
    int k = blockIdx.x;
    int t = threadIdx.x;
    float cn = counts[k];
    float4 d4 = ((const float4*)&dict[(size_t)k * CD])[t];
    float4 e4;
    e4.x = __fdiv_rn(d4.x, cn); e4.y = __fdiv_rn(d4.y, cn);
    e4.z = __fdiv_rn(d4.z, cn); e4.w = __fdiv_rn(d4.w, cn);
    ((float4*)&g_e[(size_t)k * CD])[t] = e4;

    size_t p = (size_t)k * (CD / 2) + t * 2;
    __nv_bfloat162 h0, l0, h1, l1;
    split2(e4.x, e4.y, h0, l0);
    split2(e4.z, e4.w, h1, l1);
    g_eh[p] = h0; g_eh[p + 1] = h1;
    g_el[p] = l0; g_el[p + 1] = l1;

    float* ndrow = &out[OD + (size_t)k * CD + t * 4];
    float2 nd0, nd1;
    nd0.x = __fmul_rn(d4.x, MOMENTUM); nd0.y = __fmul_rn(d4.y, MOMENTUM);
    nd1.x = __fmul_rn(d4.z, MOMENTUM); nd1.y = __fmul_rn(d4.w, MOMENTUM);
    ((float2*)ndrow)[0] = nd0;
    ((float2*)ndrow)[1] = nd1;

    float pw = e4.x * e4.x + e4.y * e4.y + e4.z * e4.z + e4.w * e4.w;
    float tot = blkSum128(pw);
    if (t == 0) {
        g_nsq[k] = tot;
        g_cnt[k] = 0;
        if (k == 0) { g_loss = 0.0; g_csum = 0.0; }
    }
}

// ---------------- K2: row norms + init best ----------------
__global__ void k_prep_rows(const float* __restrict__ X) {
    int m = blockIdx.x;
    int t = threadIdx.x;
    float4 v = ((const float4*)&X[(size_t)m * CD])[t];
    float p = v.x * v.x + v.y * v.y + v.z * v.z + v.w * v.w;
    float tot = blkSum128(p);
    if (t == 0) {
        g_s1[m] = tot;
        g_best[m] = 0xFFFFFFFFFFFFFFFFULL;
    }
}

// ---------------- K3: 3x bf16-k16 mma.sync distance GEMM + argmin --------
// CTA tile 128(M)x128(N), BK=32 (2 k16 steps), 256 thr = 8 warps (2x4),
// warp tile 64x32. smem: 4 regions (Ah,Al,Bh,Bl) of 128 rows x 80B, x2 stages.
#define TBM 128
#define TBN 128
#define BKC 32
#define NCHUNK (CD / BKC)          // 16
#define RWW 20                     // words per smem row (16 data + 4 pad)
#define RWB (RWW * 4)              // 80 bytes
#define REG_BYTES (TBM * RWB)      // 10240
#define OFF_AH 0
#define OFF_AL 10240
#define OFF_BH 20480
#define OFF_BL 30720
#define STAGE_BYTES 40960
#define SMEM_TOTAL (2 * STAGE_BYTES)

__global__ void __launch_bounds__(256)
k_mma_argmin() {
    extern __shared__ char smem[];
    const uint32_t sbase = smem_u32(smem);
    const int t    = threadIdx.x;
    const int lane = t & 31;
    const int wid  = t >> 5;
    const int wm   = wid & 1;      // 2 warp rows (M)
    const int wn   = wid >> 1;     // 4 warp cols (N)
    const int mB   = blockIdx.y * TBM;
    const int nB   = blockIdx.x * TBN;

    const int grp = lane >> 2;     // 0..7
    const int qid = lane & 3;      // 0..3

    float acc[4][4][4];
    #pragma unroll
    for (int i = 0; i < 4; i++)
        #pragma unroll
        for (int j = 0; j < 4; j++)
            #pragma unroll
            for (int r = 0; r < 4; r++) acc[i][j][r] = 0.0f;

    const char* pxh = (const char*)g_xh;
    const char* pxl = (const char*)g_xl;
    const char* peh = (const char*)g_eh;
    const char* pel = (const char*)g_el;

    // stage one BK=32 chunk: 4 regions x 128 rows x 64B = 2048 cp16 / 256 thr
    #define STAGE_CHUNK(CHUNK, BUF)                                               \
        {                                                                         \
            int c0 = (CHUNK) * BKC;                                               \
            uint32_t sa = sbase + (BUF) * STAGE_BYTES;                            \
            _Pragma("unroll")                                                     \
            for (int q = 0; q < 2; q++) {                                         \
                int id  = t + q * 256;                                            \
                int row = id >> 2;                                                \
                int s   = id & 3;                                                 \
                uint32_t doff = row * RWB + s * 16;                               \
                size_t aoff = (((size_t)(mB + row) * CD + c0) << 1) + s * 16;     \
                size_t boff = (((size_t)(nB + row) * CD + c0) << 1) + s * 16;     \
                cp16(sa + OFF_AH + doff, pxh + aoff);                             \
                cp16(sa + OFF_AL + doff, pxl + aoff);                             \
                cp16(sa + OFF_BH + doff, peh + boff);                             \
                cp16(sa + OFF_BL + doff, pel + boff);                             \
            }                                                                     \
            asm volatile("cp.async.commit_group;");                               \
        }

    STAGE_CHUNK(0, 0);

    for (int ch = 0; ch < NCHUNK; ch++) {
        int buf = ch & 1;
        if (ch + 1 < NCHUNK) {
            STAGE_CHUNK(ch + 1, (ch + 1) & 1);
            asm volatile("cp.async.wait_group 1;");
        } else {
            asm volatile("cp.async.wait_group 0;");
        }
        __syncthreads();

        const uint32_t* AH = (const uint32_t*)(smem + buf * STAGE_BYTES + OFF_AH);
        const uint32_t* AL = (const uint32_t*)(smem + buf * STAGE_BYTES + OFF_AL);
        const uint32_t* BH = (const uint32_t*)(smem + buf * STAGE_BYTES + OFF_BH);
        const uint32_t* BL = (const uint32_t*)(smem + buf * STAGE_BYTES + OFF_BL);

        #pragma unroll
        for (int ks = 0; ks < 2; ks++) {
            const int koff = ks * 8 + qid;   // word offset of (2qid,2qid+1) pair
            uint32_t a_h[4][4], a_l[4][4], b_h[4][2], b_l[4][2];
            #pragma unroll
            for (int i = 0; i < 4; i++) {
                int r = (wm * 64 + i * 16 + grp) * RWW + koff;
                a_h[i][0] = AH[r];              a_h[i][1] = AH[r + 8 * RWW];
                a_h[i][2] = AH[r + 4];          a_h[i][3] = AH[r + 8 * RWW + 4];
                a_l[i][0] = AL[r];              a_l[i][1] = AL[r + 8 * RWW];
                a_l[i][2] = AL[r + 4];          a_l[i][3] = AL[r + 8 * RWW + 4];
            }
            #pragma unroll
            for (int j = 0; j < 4; j++) {
                int r = (wn * 32 + j * 8 + grp) * RWW + koff;
                b_h[j][0] = BH[r];              b_h[j][1] = BH[r + 4];
                b_l[j][0] = BL[r];              b_l[j][1] = BL[r + 4];
            }
            // each acc[i][j] receives hh, hl, lh (in that order)
            #pragma unroll
            for (int i = 0; i < 4; i++)
                #pragma unroll
                for (int j = 0; j < 4; j++) {
                    mma16(acc[i][j], a_h[i], b_h[j]);
                    mma16(acc[i][j], a_h[i], b_l[j]);
                    mma16(acc[i][j], a_l[i], b_h[j]);
                }
        }
        __syncthreads();
    }

    // epilogue: d = (s1 - 2*dot) + nsq, packed-key argmin (R3 semantics)
    #pragma unroll
    for (int i = 0; i < 4; i++) {
        int r0 = mB + wm * 64 + i * 16 + grp;
        int r1 = r0 + 8;
        float s10 = g_s1[r0];
        float s11 = g_s1[r1];
        unsigned long long k0 = 0xFFFFFFFFFFFFFFFFULL;
        unsigned long long k1 = 0xFFFFFFFFFFFFFFFFULL;
        #pragma unroll
        for (int j = 0; j < 4; j++) {
            int n0 = nB + wn * 32 + j * 8 + 2 * qid;
            float q0 = g_nsq[n0];
            float q1 = g_nsq[n0 + 1];
            float d00 = __fadd_rn(__fsub_rn(s10, __fmul_rn(2.0f, acc[i][j][0])), q0);
            float d01 = __fadd_rn(__fsub_rn(s10, __fmul_rn(2.0f, acc[i][j][1])), q1);
            float d10 = __fadd_rn(__fsub_rn(s11, __fmul_rn(2.0f, acc[i][j][2])), q0);
            float d11 = __fadd_rn(__fsub_rn(s11, __fmul_rn(2.0f, acc[i][j][3])), q1);
            unsigned long long c;
            c = ((unsigned long long)__float_as_uint(d00) << 32) | (unsigned)n0;
            k0 = k0 < c ? k0 : c;
            c = ((unsigned long long)__float_as_uint(d01) << 32) | (unsigned)(n0 + 1);
            k0 = k0 < c ? k0 : c;
            c = ((unsigned long long)__float_as_uint(d10) << 32) | (unsigned)n0;
            k1 = k1 < c ? k1 : c;
            c = ((unsigned long long)__float_as_uint(d11) << 32) | (unsigned)(n0 + 1);
            k1 = k1 < c ? k1 : c;
        }
        #pragma unroll
        for (int o = 1; o <= 2; o <<= 1) {
            unsigned long long s0 = __shfl_xor_sync(0xffffffffu, k0, o);
            unsigned long long s1v = __shfl_xor_sync(0xffffffffu, k1, o);
            k0 = k0 < s0 ? k0 : s0;
            k1 = k1 < s1v ? k1 : s1v;
        }
        if (qid == 0) {
            atomicMin(&g_best[r0], k0);
            atomicMin(&g_best[r1], k1);
        }
    }
}

// ---------------- K4: gather x_q, scatter x_sum, histogram, loss ----------
__global__ void k_assign(const float* __restrict__ X, float* __restrict__ out) {
    int m = blockIdx.x;
    int t = threadIdx.x;
    int id = (int)(g_best[m] & 0x1FFFULL);

    float4 x4 = ((const float4*)&X[(size_t)m * CD])[t];
    float4 e4 = ((const float4*)&g_e[(size_t)id * CD])[t];

    float4 q;
    q.x = __fadd_rn(x4.x, __fsub_rn(e4.x, x4.x));
    q.y = __fadd_rn(x4.y, __fsub_rn(e4.y, x4.y));
    q.z = __fadd_rn(x4.z, __fsub_rn(e4.z, x4.z));
    q.w = __fadd_rn(x4.w, __fsub_rn(e4.w, x4.w));
    ((float4*)&out[OQ + (size_t)m * CD])[t] = q;

    float dx = __fsub_rn(q.x, x4.x), dy = __fsub_rn(q.y, x4.y);
    float dz = __fsub_rn(q.z, x4.z), dw = __fsub_rn(q.w, x4.w);
    float ls = dx * dx + dy * dy + dz * dz + dw * dw;

    float* nd = &out[OD + (size_t)id * CD + t * 4];
    atomicAdd(&nd[0], x4.x);
    atomicAdd(&nd[1], x4.y);
    atomicAdd(&nd[2], x4.z);
    atomicAdd(&nd[3], x4.w);

    float tot = blkSum128(ls);
    if (t == 0) {
        atomicAdd(&g_loss, (double)tot);
        atomicAdd(&g_cnt[id], 1);
    }
}

// ---------------- K5a/K5b: counts, perplexity, loss ----------------
__global__ void k_counts(const float* __restrict__ counts, float* __restrict__ out) {
    int t = threadIdx.x;
    double s = 0.0;
    for (int k = t; k < KVOC; k += 1024) {
        float nc = __fadd_rn(__fmul_rn(counts[k], MOMENTUM), (float)g_cnt[k]);
        out[OC + k] = nc;
        s += (double)nc;
    }
    double tot = blkSum1024d(s);
    if (t == 0) g_csum = tot;
}
__global__ void k_final(float* __restrict__ out) {
    int t = threadIdx.x;
    double tot = g_csum;
    double ent = 0.0;
    for (int k = t; k < KVOC; k += 1024) {
        double p = (double)out[OC + k] / tot;
        ent += p * log(p + 1e-10);
    }
    double e = blkSum1024d(ent);
    if (t == 0) {
        out[OP] = (float)exp(-e);
        out[OL] = (float)(0.25 * g_loss / 16777216.0);
    }
}

// ---------------- launch ----------------
extern "C" void kernel_launch(void* const* d_in, const int* in_sizes, int n_in,
                              void* d_out, int out_size) {
    const float* x      = (const float*)d_in[0];
    const float* dict   = (const float*)d_in[1];
    const float* counts = (const float*)d_in[2];
    float* out = (float*)d_out;

    // Idempotent, host-side, capture-safe; called every time (no static guards).
    cudaFuncSetAttribute(k_mma_argmin, cudaFuncAttributeMaxDynamicSharedMemorySize,
                         SMEM_TOTAL);

    k_split_x<<<(M_TOK * CD / 4) / 256, 256>>>(x);
    k_prep_codes<<<KVOC, 128>>>(dict, counts, out);
    k_prep_rows<<<M_TOK, 128>>>(x);
    dim3 gm(KVOC / TBN, M_TOK / TBM);
    k_mma_argmin<<<gm, 256, SMEM_TOTAL>>>();
    k_assign<<<M_TOK, 128>>>(x, out);
    k_counts<<<1, 1024>>>(counts, out);
    k_final<<<1, 1024>>>(out);
}